// round 5
// baseline (speedup 1.0000x reference)
#include <cuda_runtime.h>
#include <cuda_bf16.h>
#include <cstdint>

// Problem constants (fixed by the dataset)
#define T_TOK   16384
#define N_EXP   16
#define DIM     2048
#define CAP     2048
#define SLOTS   (N_EXP * CAP)        // 32768
#define OUT_MAIN ((size_t)SLOTS * DIM)  // 67,108,864 floats

// Scratch (no allocs allowed in kernel_launch)
__device__ int   g_src[SLOTS];
__device__ float g_gate[SLOTS];

// ---------------------------------------------------------------------------
// Kernel 1: per-expert capacity-clipped index build.
// One block per expert (16 blocks x 1024 threads). Block-wide inclusive scan
// over the hot_mask column in chunks of 1024 tokens, carrying a running count.
// Writes src token + gate score for each claimed slot, fills the rest of the
// expert's CAP slots with invalid (-1), and emits loads[e] = min(count, CAP).
// ---------------------------------------------------------------------------
__global__ __launch_bounds__(1024, 1)
void build_index_kernel(const int* __restrict__ hot_mask,
                        const float* __restrict__ score,
                        float* __restrict__ out, long long out_size)
{
    const int e   = blockIdx.x;
    const int tid = threadIdx.x;
    const int lane = tid & 31;
    const int wid  = tid >> 5;

    __shared__ int warp_sums[32];
    __shared__ int s_running;
    if (tid == 0) s_running = 0;
    __syncthreads();

    for (int base = 0; base < T_TOK; base += 1024) {
        const int t  = base + tid;
        const int hm = (hot_mask[t * N_EXP + e] > 0) ? 1 : 0;

        // intra-warp inclusive scan
        int incl = hm;
        #pragma unroll
        for (int o = 1; o < 32; o <<= 1) {
            int n = __shfl_up_sync(0xffffffffu, incl, o);
            if (lane >= o) incl += n;
        }
        if (lane == 31) warp_sums[wid] = incl;
        __syncthreads();

        // scan warp totals (warp 0)
        if (wid == 0) {
            int w = warp_sums[lane];
            #pragma unroll
            for (int o = 1; o < 32; o <<= 1) {
                int n = __shfl_up_sync(0xffffffffu, w, o);
                if (lane >= o) w += n;
            }
            warp_sums[lane] = w;  // inclusive across warps
        }
        __syncthreads();

        const int excl = incl - hm + (wid > 0 ? warp_sums[wid - 1] : 0);
        const int pos  = s_running + excl;
        if (hm && pos < CAP) {
            g_src[e * CAP + pos]  = t;
            g_gate[e * CAP + pos] = score[t * N_EXP + e];
        }
        const int chunk_total = warp_sums[31];
        __syncthreads();
        if (tid == 0) s_running += chunk_total;
        __syncthreads();
    }

    const int count = s_running;
    const int load  = count < CAP ? count : CAP;

    // fill unused slots with invalid marker
    for (int i = load + tid; i < CAP; i += 1024) {
        g_src[e * CAP + i]  = -1;
        g_gate[e * CAP + i] = 0.0f;
    }

    // loads appended after the main output block (if the harness expects it)
    if (tid == 0 && out_size >= (long long)(OUT_MAIN + N_EXP)) {
        out[OUT_MAIN + e] = (float)load;
    }
}

// ---------------------------------------------------------------------------
// Kernel 2: gather. One block per output slot row (32768 blocks x 256 thr).
// Each row is 2048 floats = 512 float4; each thread moves 2 float4.
// Invalid slots are zero-filled (d_out is poisoned, must be written).
// ---------------------------------------------------------------------------
__global__ __launch_bounds__(256, 8)
void gather_kernel(const float4* __restrict__ in_flow, float4* __restrict__ out)
{
    const int slot = blockIdx.x;
    const int tid  = threadIdx.x;
    float4* __restrict__ o = out + (size_t)slot * (DIM / 4);

    const int   src = g_src[slot];
    const float g   = g_gate[slot];

    if (src < 0) {
        const float4 z = make_float4(0.f, 0.f, 0.f, 0.f);
        o[tid]       = z;
        o[tid + 256] = z;
    } else {
        const float4* __restrict__ r = in_flow + (size_t)src * (DIM / 4);
        float4 a = __ldg(r + tid);
        float4 b = __ldg(r + tid + 256);
        a.x *= g; a.y *= g; a.z *= g; a.w *= g;
        b.x *= g; b.y *= g; b.z *= g; b.w *= g;
        o[tid]       = a;
        o[tid + 256] = b;
    }
}

extern "C" void kernel_launch(void* const* d_in, const int* in_sizes, int n_in,
                              void* d_out, int out_size)
{
    const float* in_flow  = (const float*)d_in[0];   // [T, D] f32
    const int*   hot_mask = (const int*)  d_in[1];   // [T, E] i32
    const float* score    = (const float*)d_in[2];   // [T, E] f32
    float*       out      = (float*)d_out;

    build_index_kernel<<<N_EXP, 1024>>>(hot_mask, score, out, (long long)out_size);
    gather_kernel<<<SLOTS, 256>>>((const float4*)in_flow, (float4*)out);
}

// round 7
// speedup vs baseline: 1.3687x; 1.3687x over previous
#include <cuda_runtime.h>
#include <cuda_bf16.h>
#include <cstdint>

// Problem constants (fixed by the dataset)
#define T_TOK   16384
#define N_EXP   16
#define DIM     2048
#define CAP     2048
#define SLOTS   (N_EXP * CAP)           // 32768
#define OUT_MAIN ((size_t)SLOTS * DIM)  // 67,108,864 floats
#define ROW4    (DIM / 4)               // 512 float4 per row

#define CHUNKS  128
#define CHTOK   (T_TOK / CHUNKS)        // 128 tokens per chunk

// Device scratch (no allocs allowed)
__device__ int   g_cnt[N_EXP * CHUNKS];   // per-expert per-chunk hit counts
__device__ int   g_off[N_EXP * CHUNKS];   // exclusive chunk offsets
__device__ int   g_load[N_EXP];           // capacity-clipped loads
__device__ int   g_dst[T_TOK * 2];        // per-token destination slots (-1 = dropped)
__device__ float g_gt [T_TOK * 2];        // per-token gate scores

// ---------------------------------------------------------------------------
// A: per-chunk per-expert counts. 128 blocks x 128 threads, 1 token/thread.
// Coalesced 64B mask-row loads + warp ballots.
// ---------------------------------------------------------------------------
__global__ __launch_bounds__(CHTOK)
void count_kernel(const int4* __restrict__ hm4)
{
    const int tid  = threadIdx.x;
    const int lane = tid & 31;
    const int wid  = tid >> 5;
    const int t    = blockIdx.x * CHTOK + tid;

    int4 m[4];
    #pragma unroll
    for (int i = 0; i < 4; i++) m[i] = hm4[(size_t)t * 4 + i];
    const int* v = (const int*)m;

    unsigned bits = 0;
    #pragma unroll
    for (int e = 0; e < N_EXP; e++) bits |= (v[e] > 0 ? 1u : 0u) << e;

    __shared__ int s_cnt[4][N_EXP];
    #pragma unroll
    for (int e = 0; e < N_EXP; e++) {
        unsigned ball = __ballot_sync(0xffffffffu, (bits >> e) & 1u);
        if (lane == 0) s_cnt[wid][e] = __popc(ball);
    }
    __syncthreads();

    if (tid < N_EXP)
        g_cnt[tid * CHUNKS + blockIdx.x] =
            s_cnt[0][tid] + s_cnt[1][tid] + s_cnt[2][tid] + s_cnt[3][tid];
}

// ---------------------------------------------------------------------------
// B: exclusive scan of chunk counts per expert. 1 block, 16 warps (one/expert).
// Also emits loads (to out tail) for the zero-fill kernel.
// ---------------------------------------------------------------------------
__global__ __launch_bounds__(512)
void scan_kernel(float* __restrict__ out, long long out_size)
{
    const int lane = threadIdx.x & 31;
    const int e    = threadIdx.x >> 5;   // 16 warps = 16 experts

    int carry = 0;
    #pragma unroll
    for (int s = 0; s < CHUNKS / 32; s++) {
        int c = g_cnt[e * CHUNKS + s * 32 + lane];
        int incl = c;
        #pragma unroll
        for (int o = 1; o < 32; o <<= 1) {
            int n = __shfl_up_sync(0xffffffffu, incl, o);
            if (lane >= o) incl += n;
        }
        g_off[e * CHUNKS + s * 32 + lane] = carry + incl - c;
        carry += __shfl_sync(0xffffffffu, incl, 31);
    }
    if (lane == 0) {
        const int load = carry < CAP ? carry : CAP;
        g_load[e] = load;
        if (out_size >= (long long)(OUT_MAIN + N_EXP))
            out[OUT_MAIN + e] = (float)load;
    }
}

// ---------------------------------------------------------------------------
// C: per-token destinations. Same decomposition as A; in-chunk rank via
// ballot/popc + cross-warp shared offsets + scanned chunk base.
// ---------------------------------------------------------------------------
__global__ __launch_bounds__(CHTOK)
void dest_kernel(const int4* __restrict__ hm4, const float4* __restrict__ sc4)
{
    const int tid  = threadIdx.x;
    const int lane = tid & 31;
    const int wid  = tid >> 5;
    const int t    = blockIdx.x * CHTOK + tid;
    const unsigned lt = (1u << lane) - 1u;

    int4 m[4];
    float4 s[4];
    #pragma unroll
    for (int i = 0; i < 4; i++) {
        m[i] = hm4[(size_t)t * 4 + i];
        s[i] = sc4[(size_t)t * 4 + i];
    }
    const int*   v  = (const int*)m;
    const float* sv = (const float*)s;

    unsigned bits = 0;
    #pragma unroll
    for (int e = 0; e < N_EXP; e++) bits |= (v[e] > 0 ? 1u : 0u) << e;

    __shared__ int s_cnt[4][N_EXP];

    int      k = 0;
    int      e_sel[2] = {-1, -1};
    unsigned b_sel[2] = {0, 0};
    #pragma unroll
    for (int e = 0; e < N_EXP; e++) {
        unsigned ball = __ballot_sync(0xffffffffu, (bits >> e) & 1u);
        if (lane == 0) s_cnt[wid][e] = __popc(ball);
        if (((bits >> e) & 1u) && k < 2) { e_sel[k] = e; b_sel[k] = ball; k++; }
    }
    __syncthreads();

    #pragma unroll
    for (int j = 0; j < 2; j++) {
        int dst = -1;
        float g = 0.0f;
        if (j < k) {
            const int e = e_sel[j];
            int woff = 0;
            #pragma unroll
            for (int w = 0; w < 4; w++) if (w < wid) woff += s_cnt[w][e];
            const int pos = g_off[e * CHUNKS + blockIdx.x] + woff +
                            __popc(b_sel[j] & lt);
            if (pos < CAP) dst = e * CAP + pos;
            g = sv[e];
        }
        g_dst[t * 2 + j] = dst;
        g_gt [t * 2 + j] = g;
    }
}

// ---------------------------------------------------------------------------
// F: zero-fill empty tails. Valid slots are dense [0, load_e); only the
// contiguous tail [load_e, CAP) per expert needs zeros.
// ---------------------------------------------------------------------------
__global__ __launch_bounds__(256)
void fill_kernel(float4* __restrict__ out)
{
    const int e   = blockIdx.x;
    const int tid = threadIdx.x;
    const float4 z = make_float4(0.f, 0.f, 0.f, 0.f);
    const int load = g_load[e];
    for (int r = load + blockIdx.y; r < CAP; r += gridDim.y) {
        float4* o = out + (size_t)(e * CAP + r) * ROW4;
        o[tid]       = z;
        o[tid + 256] = z;
    }
}

// ---------------------------------------------------------------------------
// G: token-major scatter. One block per token: read the 8KB row ONCE
// (streaming, perfect coalescing/L2 behavior), write to <=2 destination rows.
// ---------------------------------------------------------------------------
__global__ __launch_bounds__(256, 8)
void scatter_kernel(const float4* __restrict__ in_flow, float4* __restrict__ out)
{
    const int t   = blockIdx.x;
    const int tid = threadIdx.x;

    const int   d0 = g_dst[t * 2 + 0];
    const int   d1 = g_dst[t * 2 + 1];
    if ((d0 | d1) < 0 && d0 < 0 && d1 < 0) return;

    const float g0 = g_gt[t * 2 + 0];
    const float g1 = g_gt[t * 2 + 1];

    const float4* __restrict__ r = in_flow + (size_t)t * ROW4;
    float4 a = __ldg(r + tid);
    float4 b = __ldg(r + tid + 256);

    if (d0 >= 0) {
        float4* o = out + (size_t)d0 * ROW4;
        o[tid]       = make_float4(a.x * g0, a.y * g0, a.z * g0, a.w * g0);
        o[tid + 256] = make_float4(b.x * g0, b.y * g0, b.z * g0, b.w * g0);
    }
    if (d1 >= 0) {
        float4* o = out + (size_t)d1 * ROW4;
        o[tid]       = make_float4(a.x * g1, a.y * g1, a.z * g1, a.w * g1);
        o[tid + 256] = make_float4(b.x * g1, b.y * g1, b.z * g1, b.w * g1);
    }
}

extern "C" void kernel_launch(void* const* d_in, const int* in_sizes, int n_in,
                              void* d_out, int out_size)
{
    const float* in_flow  = (const float*)d_in[0];   // [T, D] f32
    const int*   hot_mask = (const int*)  d_in[1];   // [T, E] i32
    const float* score    = (const float*)d_in[2];   // [T, E] f32
    float*       out      = (float*)d_out;

    count_kernel<<<CHUNKS, CHTOK>>>((const int4*)hot_mask);
    scan_kernel<<<1, 512>>>(out, (long long)out_size);
    dest_kernel<<<CHUNKS, CHTOK>>>((const int4*)hot_mask, (const float4*)score);
    fill_kernel<<<dim3(N_EXP, 8), 256>>>((float4*)out);
    scatter_kernel<<<T_TOK, 256>>>((const float4*)in_flow, (float4*)out);
}

// round 8
// speedup vs baseline: 1.5268x; 1.1155x over previous
#include <cuda_runtime.h>
#include <cuda_bf16.h>
#include <cstdint>

// Problem constants (fixed by the dataset)
#define T_TOK   16384
#define N_EXP   16
#define DIM     2048
#define CAP     2048
#define SLOTS   (N_EXP * CAP)           // 32768
#define OUT_MAIN ((size_t)SLOTS * DIM)  // 67,108,864 floats
#define ROW4    (DIM / 4)               // 512 float4 per row

#define CHUNKS  128
#define CHTOK   (T_TOK / CHUNKS)        // 128 tokens per chunk
#define FILLB   (N_EXP * 8)             // fill helper blocks in scatter grid

// Device scratch (no allocs allowed)
__device__ int   g_cnt[N_EXP * CHUNKS];   // per-expert per-chunk hit counts
__device__ int   g_load[N_EXP];           // capacity-clipped loads
__device__ int   g_dst[T_TOK * 2];        // per-token destination slots (-1 = dropped)
__device__ float g_gt [T_TOK * 2];        // per-token gate scores

// ---------------------------------------------------------------------------
// A: per-chunk per-expert counts. 128 blocks x 128 threads, 1 token/thread.
// ---------------------------------------------------------------------------
__global__ __launch_bounds__(CHTOK)
void count_kernel(const int4* __restrict__ hm4)
{
    const int tid  = threadIdx.x;
    const int lane = tid & 31;
    const int wid  = tid >> 5;
    const int t    = blockIdx.x * CHTOK + tid;

    int4 m[4];
    #pragma unroll
    for (int i = 0; i < 4; i++) m[i] = hm4[(size_t)t * 4 + i];
    const int* v = (const int*)m;

    unsigned bits = 0;
    #pragma unroll
    for (int e = 0; e < N_EXP; e++) bits |= (v[e] > 0 ? 1u : 0u) << e;

    __shared__ int s_cnt[4][N_EXP];
    #pragma unroll
    for (int e = 0; e < N_EXP; e++) {
        unsigned ball = __ballot_sync(0xffffffffu, (bits >> e) & 1u);
        if (lane == 0) s_cnt[wid][e] = __popc(ball);
    }
    __syncthreads();

    if (tid < N_EXP)
        g_cnt[tid * CHUNKS + blockIdx.x] =
            s_cnt[0][tid] + s_cnt[1][tid] + s_cnt[2][tid] + s_cnt[3][tid];
}

// ---------------------------------------------------------------------------
// B (fused scan+dest): each block redundantly computes its own exclusive
// chunk offsets from g_cnt (8KB, L2-hot), then per-token ranks/destinations.
// Last chunk block also emits loads.
// ---------------------------------------------------------------------------
__global__ __launch_bounds__(CHTOK)
void dest_kernel(const int4* __restrict__ hm4, const float4* __restrict__ sc4,
                 float* __restrict__ out, long long out_size)
{
    const int tid  = threadIdx.x;
    const int lane = tid & 31;
    const int wid  = tid >> 5;
    const int t    = blockIdx.x * CHTOK + tid;
    const unsigned lt = (1u << lane) - 1u;

    int4 m[4];
    float4 s[4];
    #pragma unroll
    for (int i = 0; i < 4; i++) {
        m[i] = hm4[(size_t)t * 4 + i];
        s[i] = sc4[(size_t)t * 4 + i];
    }
    const int*   v  = (const int*)m;
    const float* sv = (const float*)s;

    unsigned bits = 0;
    #pragma unroll
    for (int e = 0; e < N_EXP; e++) bits |= (v[e] > 0 ? 1u : 0u) << e;

    __shared__ int s_cnt[4][N_EXP];
    __shared__ int s_off[N_EXP];

    int      k = 0;
    int      e_sel[2] = {-1, -1};
    unsigned b_sel[2] = {0, 0};
    #pragma unroll
    for (int e = 0; e < N_EXP; e++) {
        unsigned ball = __ballot_sync(0xffffffffu, (bits >> e) & 1u);
        if (lane == 0) s_cnt[wid][e] = __popc(ball);
        if (((bits >> e) & 1u) && k < 2) { e_sel[k] = e; b_sel[k] = ball; k++; }
    }

    // Inline exclusive scan over chunk counts: thread tid handles expert
    // (tid>>3), chunk segment (tid&7)*16..+15; 8-thread shfl reduction.
    {
        const int me  = tid >> 3;       // 0..15
        const int seg = tid & 7;        // 0..7
        int partial = 0;
        #pragma unroll
        for (int i = 0; i < 16; i++) {
            const int c = seg * 16 + i;
            if (c < blockIdx.x) partial += g_cnt[me * CHUNKS + c];
        }
        #pragma unroll
        for (int o = 4; o >= 1; o >>= 1)
            partial += __shfl_down_sync(0xffffffffu, partial, o, 8);
        if (seg == 0) s_off[me] = partial;
    }
    __syncthreads();

    // Last chunk block knows the totals -> loads.
    if (blockIdx.x == CHUNKS - 1 && tid < N_EXP) {
        const int tot = s_off[tid] + s_cnt[0][tid] + s_cnt[1][tid] +
                        s_cnt[2][tid] + s_cnt[3][tid];
        const int load = tot < CAP ? tot : CAP;
        g_load[tid] = load;
        if (out_size >= (long long)(OUT_MAIN + N_EXP))
            out[OUT_MAIN + tid] = (float)load;
    }

    #pragma unroll
    for (int j = 0; j < 2; j++) {
        int dst = -1;
        float g = 0.0f;
        if (j < k) {
            const int e = e_sel[j];
            int woff = 0;
            #pragma unroll
            for (int w = 0; w < 4; w++) if (w < wid) woff += s_cnt[w][e];
            const int pos = s_off[e] + woff + __popc(b_sel[j] & lt);
            if (pos < CAP) dst = e * CAP + pos;
            g = sv[e];
        }
        g_dst[t * 2 + j] = dst;
        g_gt [t * 2 + j] = g;
    }
}

// ---------------------------------------------------------------------------
// C: fused fill + token-major scatter.
// Blocks [0, FILLB): zero-fill expert tails [load_e, CAP).
// Blocks [FILLB, FILLB+T_TOK): read token row once, write <=2 dest rows.
// Streaming hints (__ldcs/__stcs): no reuse, keep L2 from thrashing.
// ---------------------------------------------------------------------------
__device__ __forceinline__ void st_row4(float4* p, float4 a)
{
    __stcs(p, a);
}

__global__ __launch_bounds__(256, 8)
void scatter_kernel(const float4* __restrict__ in_flow, float4* __restrict__ out)
{
    const int tid = threadIdx.x;

    if (blockIdx.x < FILLB) {
        const int f = blockIdx.x;
        const int e = f >> 3;
        const int y = f & 7;
        const float4 z = make_float4(0.f, 0.f, 0.f, 0.f);
        const int load = g_load[e];
        for (int r = load + y; r < CAP; r += 8) {
            float4* o = out + (size_t)(e * CAP + r) * ROW4;
            st_row4(o + tid, z);
            st_row4(o + tid + 256, z);
        }
        return;
    }

    const int t = blockIdx.x - FILLB;

    const int d0 = g_dst[t * 2 + 0];
    const int d1 = g_dst[t * 2 + 1];
    if (d0 < 0 && d1 < 0) return;

    const float g0 = g_gt[t * 2 + 0];
    const float g1 = g_gt[t * 2 + 1];

    const float4* __restrict__ r = in_flow + (size_t)t * ROW4;
    float4 a = __ldcs(r + tid);
    float4 b = __ldcs(r + tid + 256);

    if (d0 >= 0) {
        float4* o = out + (size_t)d0 * ROW4;
        st_row4(o + tid,       make_float4(a.x * g0, a.y * g0, a.z * g0, a.w * g0));
        st_row4(o + tid + 256, make_float4(b.x * g0, b.y * g0, b.z * g0, b.w * g0));
    }
    if (d1 >= 0) {
        float4* o = out + (size_t)d1 * ROW4;
        st_row4(o + tid,       make_float4(a.x * g1, a.y * g1, a.z * g1, a.w * g1));
        st_row4(o + tid + 256, make_float4(b.x * g1, b.y * g1, b.z * g1, b.w * g1));
    }
}

extern "C" void kernel_launch(void* const* d_in, const int* in_sizes, int n_in,
                              void* d_out, int out_size)
{
    const float* in_flow  = (const float*)d_in[0];   // [T, D] f32
    const int*   hot_mask = (const int*)  d_in[1];   // [T, E] i32
    const float* score    = (const float*)d_in[2];   // [T, E] f32
    float*       out      = (float*)d_out;

    count_kernel<<<CHUNKS, CHTOK>>>((const int4*)hot_mask);
    dest_kernel<<<CHUNKS, CHTOK>>>((const int4*)hot_mask, (const float4*)score,
                                   out, (long long)out_size);
    scatter_kernel<<<T_TOK + FILLB, 256>>>((const float4*)in_flow, (float4*)out);
}